// round 16
// baseline (speedup 1.0000x reference)
#include <cuda_runtime.h>
#include <cuda_fp16.h>
#include <cstdint>

#define T_SEQ  2048
#define NHEAD  16
#define HDIM   128
#define BATCH  2
#define CDIM   2048
#define MROWS  (BATCH * T_SEQ)   // 4096

// ---------------------------------------------------------------------------
// Device-global scratch (allocation-free, graph-safe), fp16
// Q carries hi/lo (exact); x, W, K, V, Y are fp16-rounded.
// ---------------------------------------------------------------------------
__device__ __half g_xh[(size_t)MROWS * CDIM];
__device__ __half g_Wh[4][(size_t)CDIM * CDIM];   // q,k,v,p
__device__ __half g_Qh[(size_t)BATCH * NHEAD * T_SEQ * HDIM];
__device__ __half g_Ql[(size_t)BATCH * NHEAD * T_SEQ * HDIM];
__device__ __half g_Kh[(size_t)BATCH * NHEAD * T_SEQ * HDIM];
__device__ __half g_Vh[(size_t)BATCH * NHEAD * T_SEQ * HDIM];
__device__ __half g_Yh[(size_t)BATCH * T_SEQ * CDIM];   // [b][c][t]

// ===========================================================================
// helpers
// ===========================================================================
__device__ __forceinline__ uint32_t smem_to_u32(const void* p) {
    uint32_t a;
    asm("{ .reg .u64 t; cvta.to.shared.u64 t, %1; cvt.u32.u64 %0, t; }"
        : "=r"(a) : "l"(p));
    return a;
}

__device__ __forceinline__ uint32_t hfp(float a, float b) {
    __half2 t = __floats2half2_rn(a, b);
    return *reinterpret_cast<uint32_t*>(&t);
}
__device__ __forceinline__ float hres(float a) {
    return a - __half2float(__float2half_rn(a));
}

#define LDMX4(r0, r1, r2, r3, addr) \
    asm volatile("ldmatrix.sync.aligned.m8n8.x4.shared.b16 {%0,%1,%2,%3}, [%4];" \
                 : "=r"(r0), "=r"(r1), "=r"(r2), "=r"(r3) : "r"(addr))

#define LDMX4T(r0, r1, r2, r3, addr) \
    asm volatile("ldmatrix.sync.aligned.m8n8.x4.trans.shared.b16 {%0,%1,%2,%3}, [%4];" \
                 : "=r"(r0), "=r"(r1), "=r"(r2), "=r"(r3) : "r"(addr))

#define MMA16816(c, a, b0, b1) \
    asm volatile("mma.sync.aligned.m16n8k16.row.col.f32.f16.f16.f32 " \
                 "{%0,%1,%2,%3}, {%4,%5,%6,%7}, {%8,%9}, {%0,%1,%2,%3};" \
                 : "+f"((c)[0]), "+f"((c)[1]), "+f"((c)[2]), "+f"((c)[3]) \
                 : "r"((a)[0]), "r"((a)[1]), "r"((a)[2]), "r"((a)[3]), \
                   "r"(b0), "r"(b1))

#define STSV4(addr, a, b, cc, d) \
    asm volatile("st.shared.v4.b32 [%0], {%1,%2,%3,%4};" \
                 :: "r"(addr), "r"(a), "r"(b), "r"(cc), "r"(d) : "memory")

#define CPASYNC16(saddr, gptr) \
    asm volatile("cp.async.cg.shared.global [%0], [%1], 16;" \
                 :: "r"(saddr), "l"(gptr) : "memory")
#define CPCOMMIT() asm volatile("cp.async.commit_group;" ::: "memory")
#define CPWAIT1()  asm volatile("cp.async.wait_group 1;" ::: "memory")
#define CPWAIT0()  asm volatile("cp.async.wait_group 0;" ::: "memory")

// ===========================================================================
// fused fp32 -> fp16 conversion: x + 4 weights, all hi-only, ONE launch
// ===========================================================================
#define N4X (MROWS * CDIM / 4)
#define N4W (CDIM * CDIM / 4)

__global__ void cvt_all(const float* __restrict__ x, __half* __restrict__ xh,
                        const float* __restrict__ Wq, const float* __restrict__ Wk,
                        const float* __restrict__ Wv, const float* __restrict__ Wp,
                        __half* __restrict__ Wh)
{
    const int i = blockIdx.x * blockDim.x + threadIdx.x;
    if (i < N4X) {
        const float4 v = ((const float4*)x)[i];
        uint2 h;
        h.x = hfp(v.x, v.y); h.y = hfp(v.z, v.w);
        ((uint2*)xh)[i] = h;
    } else {
        const int j = i - N4X;
        const int mat = j >> 20;            // j / N4W (N4W = 2^20)
        const int k   = j & (N4W - 1);
        if (mat < 4) {
            const float* W = (mat == 0) ? Wq : (mat == 1) ? Wk
                                             : (mat == 2) ? Wv : Wp;
            const float4 v = ((const float4*)W)[k];
            uint2 h;
            h.x = hfp(v.x, v.y); h.y = hfp(v.z, v.w);
            ((uint2*)(Wh + (size_t)mat * CDIM * CDIM))[k] = h;
        }
    }
}

// ===========================================================================
// Tensor-core GEMM, fp16 1-pass: C(M,N) = A(M,K) @ W(N,K)^T + bias(N).
// CTA tile 128x128, warp tile 32x64 (8 warps = 4m x 2n), K-chunk 64,
// 3-stage cp.async pipeline (96KB) -> 2 CTAs/SM, 1 sync/chunk.
// MODE 0: fp32 C out (grid 16 x 32).  MODE 1: fused QKV (grid.x=48, mat=bx>>4)
// Per-stage (32KB): Ah 0 (16K), Bh 16K (16K).   (unchanged from R13)
// ===========================================================================
#define GEMM_SMEM_BYTES 98304

template <int MODE>
__global__ void __launch_bounds__(256, 2)
gemm_h(const __half* __restrict__ Ah, const __half* __restrict__ Wh,
       const float* __restrict__ b0, const float* __restrict__ b1,
       const float* __restrict__ b2,
       float* __restrict__ C,
       __half* __restrict__ Qo, __half* __restrict__ Qlo,
       __half* __restrict__ Ko, __half* __restrict__ Vo)
{
    extern __shared__ __align__(1024) char sm[];
    const uint32_t sbase = smem_to_u32(sm);

    const int tid  = threadIdx.x;
    const int wid  = tid >> 5;
    const int lane = tid & 31;
    const int wm   = wid >> 1;        // 0..3 -> rows wm*32
    const int wn   = wid & 1;         // 0..1 -> cols wn*64
    const int quad = lane >> 3;
    const int rr   = lane & 7;
    const int mat  = (MODE == 1) ? ((int)blockIdx.x >> 4) : 0;
    const int nbx  = (MODE == 1) ? ((int)blockIdx.x & 15) : (int)blockIdx.x;
    const int mBase = blockIdx.y * 128;
    const int nBase = nbx * 128;

    const __half* Agh = Ah + (size_t)mBase * CDIM;
    const __half* Bgh = Wh + (size_t)mat * CDIM * CDIM + (size_t)nBase * CDIM;
    const float* bias = (MODE == 0) ? b0 : (mat == 0 ? b0 : (mat == 1 ? b1 : b2));

    float c[2][8][4];
#pragma unroll
    for (int mi = 0; mi < 2; mi++)
#pragma unroll
        for (int ni = 0; ni < 8; ni++)
#pragma unroll
            for (int k = 0; k < 4; k++) c[mi][ni][k] = 0.f;

    const int arow0 = wm * 32 + (quad & 1) * 8 + rr;
    const int acolq = (quad >> 1) * 8;
    const int brow0 = wn * 64 + (quad >> 1) * 8 + rr;
    const int bcolq = (quad & 1) * 8;

    auto stage_load = [&](int kt, int stg) {
        const uint32_t base = sbase + (uint32_t)stg * 32768u;
#pragma unroll
        for (int i = 0; i < 4; i++) {
            const int idx = tid + 256 * i;
            const int r = idx >> 3, g = idx & 7;
            const uint32_t off = (uint32_t)(r * 128 + g * 16);
            const uint32_t sw  = off ^ ((off >> 3) & 0x70);
            const size_t e = (size_t)r * CDIM + kt * 64 + g * 8;
            CPASYNC16(base + sw,          (const char*)(Agh + e));
            CPASYNC16(base + 16384u + sw, (const char*)(Bgh + e));
        }
    };

    auto compute = [&](int stg) {
        const uint32_t base = sbase + (uint32_t)stg * 32768u;
        const uint32_t AhS = base, BhS = base + 16384u;
#pragma unroll
        for (int sub = 0; sub < 4; sub++) {
            const int kb = sub * 16;
            uint32_t bh[16];
#pragma unroll
            for (int p = 0; p < 4; p++) {
                const uint32_t off = (uint32_t)((brow0 + p * 16) * 128 + (kb + bcolq) * 2);
                const uint32_t sw  = off ^ ((off >> 3) & 0x70);
                LDMX4(bh[4 * p], bh[4 * p + 1], bh[4 * p + 2], bh[4 * p + 3], BhS + sw);
            }
#pragma unroll
            for (int mi = 0; mi < 2; mi++) {
                uint32_t ah[4];
                const uint32_t off = (uint32_t)((arow0 + mi * 16) * 128 + (kb + acolq) * 2);
                const uint32_t sw  = off ^ ((off >> 3) & 0x70);
                LDMX4(ah[0], ah[1], ah[2], ah[3], AhS + sw);
#pragma unroll
                for (int ni = 0; ni < 8; ni++)
                    MMA16816(c[mi][ni], ah, bh[2 * ni], bh[2 * ni + 1]);
            }
        }
    };

    stage_load(0, 0); CPCOMMIT();
    stage_load(1, 1); CPCOMMIT();

    int stg = 0;
    for (int kt = 0; kt < 32; kt++) {
        if (kt + 1 < 32) { CPWAIT1(); } else { CPWAIT0(); }
        __syncthreads();
        if (kt + 2 < 32) {
            int ns = stg + 2; if (ns >= 3) ns -= 3;
            stage_load(kt + 2, ns);
            CPCOMMIT();
        }
        compute(stg);
        if (++stg == 3) stg = 0;
    }

    // epilogue: fragments -> smem Ct[128][132] fp32 -> gmem
    __syncthreads();
    float* Ct = (float*)sm;
    const int g2 = lane >> 2, t2 = (lane & 3) * 2;
#pragma unroll
    for (int mi = 0; mi < 2; mi++) {
        const int row = wm * 32 + mi * 16 + g2;
#pragma unroll
        for (int ni = 0; ni < 8; ni++) {
            const int col = wn * 64 + ni * 8 + t2;
            Ct[row * 132 + col]           = c[mi][ni][0];
            Ct[row * 132 + col + 1]       = c[mi][ni][1];
            Ct[(row + 8) * 132 + col]     = c[mi][ni][2];
            Ct[(row + 8) * 132 + col + 1] = c[mi][ni][3];
        }
    }
    __syncthreads();

    for (int idx = tid; idx < 128 * 32; idx += 256) {
        const int row = idx >> 5, c4 = (idx & 31) * 4;
        const int n = nBase + c4;
        const float4 bv = *(const float4*)&bias[n];
        float4 v;
        v.x = Ct[row * 132 + c4]     + bv.x;
        v.y = Ct[row * 132 + c4 + 1] + bv.y;
        v.z = Ct[row * 132 + c4 + 2] + bv.z;
        v.w = Ct[row * 132 + c4 + 3] + bv.w;
        const int m = mBase + row;
        if (MODE == 0) {
            *(float4*)&C[(size_t)m * CDIM + n] = v;
        } else {
            const int b = m >> 11, t = m & (T_SEQ - 1);
            const int h = n >> 7, d = n & (HDIM - 1);
            const size_t e = (((size_t)(b * NHEAD + h)) * T_SEQ + t) * HDIM + d;
            uint2 hh;
            hh.x = hfp(v.x, v.y); hh.y = hfp(v.z, v.w);
            if (mat == 0) {
                uint2 ll;
                ll.x = hfp(hres(v.x), hres(v.y)); ll.y = hfp(hres(v.z), hres(v.w));
                *(uint2*)(Qo + e)  = hh;
                *(uint2*)(Qlo + e) = ll;
            } else {
                __half* dst = (mat == 1) ? Ko : Vo;
                *(uint2*)(dst + e) = hh;
            }
        }
    }
}

// ===========================================================================
// FA2-style tensor-core flash attention, causal, fp16 (Q hi/lo exact,
// K/V fp16, P hi/lo in regs — R13 numerics bit-identical).
// BQ=64, 128 threads (4 warps), 96KB smem -> 2 independent CTAs/SM with
// NO register cap (launch_bounds(128,2) allows up to 255 regs).
// smem: Qh 0 (16K), Ql 16K; KV buf b at 32K + b*32K: KH (16K), VH (16K).
// ===========================================================================
#define ATTN_SMEM_BYTES 98304

__global__ void __launch_bounds__(128, 2)
attn_mma(const __half* __restrict__ Qh, const __half* __restrict__ Ql,
         const __half* __restrict__ Kh, const __half* __restrict__ Vh,
         __half* __restrict__ Yh)
{
    extern __shared__ __align__(1024) char sm[];
    const uint32_t sb = smem_to_u32(sm);
    const uint32_t QHs = sb, QLs = sb + 16384u;

    const int tid  = threadIdx.x;
    const int lane = tid & 31;
    const int w    = tid >> 5;        // warp 0..3 -> q rows w*16
    const int quad = lane >> 3;
    const int rr   = lane & 7;
    const int g    = lane >> 2;
    const int tq   = lane & 3;
    const int qb   = (int)gridDim.x - 1 - (int)blockIdx.x;  // heavy first
    const int bh   = blockIdx.y;

    const size_t headbase = (size_t)bh * T_SEQ * HDIM;
    const int jend = qb;              // 64-key blocks, causal

    auto stage_kv = [&](int jb, int b) {
        const size_t base = headbase + (size_t)jb * 64 * HDIM;
        const char* kh = (const char*)(Kh + base);
        const char* vh = (const char*)(Vh + base);
        const uint32_t bufb = sb + 32768u + (uint32_t)b * 32768u;
#pragma unroll
        for (int i = 0; i < 8; i++) {
            const int c = tid + 128 * i;
            const int row = c >> 4, gg = c & 15;
            const uint32_t off = (uint32_t)row * 256u +
                                 ((uint32_t)(gg * 16) ^ ((uint32_t)(row & 7) << 4));
            const size_t gb = (size_t)c * 16;
            CPASYNC16(bufb + off,          kh + gb);
            CPASYNC16(bufb + 16384u + off, vh + gb);
        }
    };

    stage_kv(0, 0);
    CPCOMMIT();
    {
        const size_t base = headbase + (size_t)qb * 64 * HDIM;
        const uint4* qh4 = (const uint4*)(Qh + base);
        const uint4* ql4 = (const uint4*)(Ql + base);
#pragma unroll
        for (int i = 0; i < 8; i++) {
            const int c = tid + 128 * i;
            const int row = c >> 4, gg = c & 15;
            const uint32_t off = (uint32_t)row * 256u +
                                 ((uint32_t)(gg * 16) ^ ((uint32_t)(row & 7) << 4));
            const uint4 vh = qh4[c], vl = ql4[c];
            STSV4(QHs + off, vh.x, vh.y, vh.z, vh.w);
            STSV4(QLs + off, vl.x, vl.y, vl.z, vl.w);
        }
    }

    float o[16][4];
#pragma unroll
    for (int nd = 0; nd < 16; nd++)
#pragma unroll
        for (int k = 0; k < 4; k++) o[nd][k] = 0.f;
    float m_i[2] = {-1e30f, -1e30f}, l_i[2] = {0.f, 0.f};

    const float scale = 0.08838834764831845f;   // 1/sqrt(128)
    const int R0 = qb * 64 + w * 16;

    for (int jb = 0; jb <= jend; jb++) {
        const int buf = jb & 1;
        if (jb < jend) { stage_kv(jb + 1, buf ^ 1); CPCOMMIT(); }
        if (jb < jend) { CPWAIT1(); } else { CPWAIT0(); }
        __syncthreads();

        {
            const uint32_t KHb = sb + 32768u + (uint32_t)buf * 32768u;
            const uint32_t VHb = KHb + 16384u;

            // ---- S = Q K^T : 16 rows x 64 keys, 2-pass (Q hi/lo, K fp16) ----
            float s[8][4];
#pragma unroll
            for (int ni = 0; ni < 8; ni++)
#pragma unroll
                for (int k = 0; k < 4; k++) s[ni][k] = 0.f;

#pragma unroll
            for (int kb = 0; kb < 8; kb++) {
                uint32_t ah[4], al[4];
                {
                    const int arow = w * 16 + (quad & 1) * 8 + rr;
                    const uint32_t cb = (uint32_t)(kb * 32 + (quad >> 1) * 16);
                    const uint32_t off = (uint32_t)arow * 256u +
                                         (cb ^ ((uint32_t)(arow & 7) << 4));
                    LDMX4(ah[0], ah[1], ah[2], ah[3], QHs + off);
                    LDMX4(al[0], al[1], al[2], al[3], QLs + off);
                }
#pragma unroll
                for (int p = 0; p < 4; p++) {
                    uint32_t bh2[4];
                    const int krow = p * 16 + (quad >> 1) * 8 + rr;
                    const uint32_t cb = (uint32_t)(kb * 32 + (quad & 1) * 16);
                    const uint32_t off = (uint32_t)krow * 256u +
                                         (cb ^ ((uint32_t)(krow & 7) << 4));
                    LDMX4(bh2[0], bh2[1], bh2[2], bh2[3], KHb + off);
                    MMA16816(s[2 * p],     ah, bh2[0], bh2[1]);
                    MMA16816(s[2 * p],     al, bh2[0], bh2[1]);
                    MMA16816(s[2 * p + 1], ah, bh2[2], bh2[3]);
                    MMA16816(s[2 * p + 1], al, bh2[2], bh2[3]);
                }
            }

            // ---- scale + causal mask ----
            const bool needmask = (jb * 64 + 63 > R0);
#pragma unroll
            for (int ni = 0; ni < 8; ni++)
#pragma unroll
                for (int j = 0; j < 4; j++) {
                    float v = s[ni][j] * scale;
                    if (needmask) {
                        const int rglob = R0 + g + ((j >> 1) << 3);
                        const int kglob = jb * 64 + ni * 8 + 2 * tq + (j & 1);
                        if (kglob > rglob) v = -1e30f;
                    }
                    s[ni][j] = v;
                }

            // ---- warp-local online softmax (rows g, g+8) ----
            float alpha[2];
#pragma unroll
            for (int r = 0; r < 2; r++) {
                float mx = -1e30f;
#pragma unroll
                for (int ni = 0; ni < 8; ni++)
                    mx = fmaxf(mx, fmaxf(s[ni][2 * r], s[ni][2 * r + 1]));
                mx = fmaxf(mx, __shfl_xor_sync(0xffffffffu, mx, 1));
                mx = fmaxf(mx, __shfl_xor_sync(0xffffffffu, mx, 2));
                const float mn = fmaxf(m_i[r], mx);
                alpha[r] = __expf(m_i[r] - mn);
                m_i[r] = mn;
                float sum = 0.f;
#pragma unroll
                for (int ni = 0; ni < 8; ni++) {
                    const float p0 = __expf(s[ni][2 * r] - mn);
                    const float p1 = __expf(s[ni][2 * r + 1] - mn);
                    s[ni][2 * r] = p0; s[ni][2 * r + 1] = p1;
                    sum += p0 + p1;
                }
                sum += __shfl_xor_sync(0xffffffffu, sum, 1);
                sum += __shfl_xor_sync(0xffffffffu, sum, 2);
                l_i[r] = l_i[r] * alpha[r] + sum;
#pragma unroll
                for (int nd = 0; nd < 16; nd++) {
                    o[nd][2 * r]     *= alpha[r];
                    o[nd][2 * r + 1] *= alpha[r];
                }
            }

            // ---- O += P V : P hi/lo packed in regs, V fp16 (2-pass) ----
#pragma unroll
            for (int kc = 0; kc < 4; kc++) {
                uint32_t aph[4], apl[4];
                const float* s0 = s[2 * kc];
                const float* s1 = s[2 * kc + 1];
                aph[0] = hfp(s0[0], s0[1]);
                aph[1] = hfp(s0[2], s0[3]);
                aph[2] = hfp(s1[0], s1[1]);
                aph[3] = hfp(s1[2], s1[3]);
                apl[0] = hfp(hres(s0[0]), hres(s0[1]));
                apl[1] = hfp(hres(s0[2]), hres(s0[3]));
                apl[2] = hfp(hres(s1[0]), hres(s1[1]));
                apl[3] = hfp(hres(s1[2]), hres(s1[3]));
#pragma unroll
                for (int nd = 0; nd < 8; nd++) {
                    const int key = kc * 16 + (quad & 1) * 8 + rr;
                    const uint32_t db = (uint32_t)(nd * 32 + (quad >> 1) * 16);
                    const uint32_t off = (uint32_t)key * 256u +
                                         (db ^ ((uint32_t)(key & 7) << 4));
                    uint32_t vh[4];
                    LDMX4T(vh[0], vh[1], vh[2], vh[3], VHb + off);
                    MMA16816(o[2 * nd],     aph, vh[0], vh[1]);
                    MMA16816(o[2 * nd],     apl, vh[0], vh[1]);
                    MMA16816(o[2 * nd + 1], aph, vh[2], vh[3]);
                    MMA16816(o[2 * nd + 1], apl, vh[2], vh[3]);
                }
            }
        }
        __syncthreads();
    }

    // ---- epilogue: normalize, transpose-stage, store Y fp16 [d][t] ----
    const float inv0 = 1.f / l_i[0], inv1 = 1.f / l_i[1];
    float* Od = (float*)sm;   // [128 d][68]
#pragma unroll
    for (int nd = 0; nd < 16; nd++) {
        const int d = nd * 8 + 2 * tq;
        const int t0 = w * 16 + g;
        Od[d * 68 + t0]           = o[nd][0] * inv0;
        Od[(d + 1) * 68 + t0]     = o[nd][1] * inv0;
        Od[d * 68 + t0 + 8]       = o[nd][2] * inv1;
        Od[(d + 1) * 68 + t0 + 8] = o[nd][3] * inv1;
    }
    __syncthreads();

    const int b = bh >> 4, h = bh & 15;
    const size_t ybase = ((size_t)(b * CDIM + h * HDIM)) * T_SEQ + (size_t)qb * 64;
    for (int idx = tid; idx < 128 * 16; idx += 128) {
        const int d = idx >> 4, q4 = (idx & 15) * 4;
        const float4 v = *(const float4*)&Od[d * 68 + q4];
        uint2 hh;
        hh.x = hfp(v.x, v.y); hh.y = hfp(v.z, v.w);
        *(uint2*)(Yh + ybase + (size_t)d * T_SEQ + q4) = hh;
    }
}

// ===========================================================================
extern "C" void kernel_launch(void* const* d_in, const int* in_sizes, int n_in,
                              void* d_out, int out_size)
{
    (void)in_sizes; (void)n_in; (void)out_size;
    const float* x  = (const float*)d_in[0];
    const float* Wq = (const float*)d_in[1];
    const float* bq = (const float*)d_in[2];
    const float* Wk = (const float*)d_in[3];
    const float* bk = (const float*)d_in[4];
    const float* Wv = (const float*)d_in[5];
    const float* bv = (const float*)d_in[6];
    const float* Wp = (const float*)d_in[7];
    const float* bp = (const float*)d_in[8];
    float* out = (float*)d_out;

    __half *xh, *Wh, *Qh, *Ql, *Kh, *Vh, *Yh;
    cudaGetSymbolAddress((void**)&xh, g_xh);
    cudaGetSymbolAddress((void**)&Wh, g_Wh);
    cudaGetSymbolAddress((void**)&Qh, g_Qh);
    cudaGetSymbolAddress((void**)&Ql, g_Ql);
    cudaGetSymbolAddress((void**)&Kh, g_Kh);
    cudaGetSymbolAddress((void**)&Vh, g_Vh);
    cudaGetSymbolAddress((void**)&Yh, g_Yh);

    cudaFuncSetAttribute(gemm_h<0>, cudaFuncAttributeMaxDynamicSharedMemorySize,
                         GEMM_SMEM_BYTES);
    cudaFuncSetAttribute(gemm_h<1>, cudaFuncAttributeMaxDynamicSharedMemorySize,
                         GEMM_SMEM_BYTES);
    cudaFuncSetAttribute(attn_mma, cudaFuncAttributeMaxDynamicSharedMemorySize,
                         ATTN_SMEM_BYTES);

    const size_t WSZ = (size_t)CDIM * CDIM;

    // fused conversion pass (x + all 4 weights, fp16)
    {
        const int total = N4X + 4 * N4W;
        cvt_all<<<(total + 255) / 256, 256>>>(x, xh, Wq, Wk, Wv, Wp, Wh);
    }

    // fused QKV GEMM: grid.x = 3 mats x 16 n-tiles, grid.y = 32 m-tiles
    gemm_h<1><<<dim3(48, MROWS / 128), 256, GEMM_SMEM_BYTES>>>(
        xh, Wh, bq, bk, bv, nullptr, Qh, Ql, Kh, Vh);

    attn_mma<<<dim3(T_SEQ / 64, BATCH * NHEAD), 128, ATTN_SMEM_BYTES>>>(
        Qh, Ql, Kh, Vh, Yh);

    gemm_h<0><<<dim3(16, MROWS / 128), 256, GEMM_SMEM_BYTES>>>(
        Yh, Wh + 3 * WSZ, bp, nullptr, nullptr, out,
        nullptr, nullptr, nullptr, nullptr);
}

// round 17
// speedup vs baseline: 1.7690x; 1.7690x over previous
#include <cuda_runtime.h>
#include <cuda_fp16.h>
#include <cstdint>

#define T_SEQ  2048
#define NHEAD  16
#define HDIM   128
#define BATCH  2
#define CDIM   2048
#define MROWS  (BATCH * T_SEQ)   // 4096

// ---------------------------------------------------------------------------
// Device-global scratch (allocation-free, graph-safe), fp16 (all 1-pass
// rounded except P which stays hi/lo in registers inside attention).
// ---------------------------------------------------------------------------
__device__ __half g_xh[(size_t)MROWS * CDIM];
__device__ __half g_Wh[4][(size_t)CDIM * CDIM];   // q,k,v,p
__device__ __half g_Qh[(size_t)BATCH * NHEAD * T_SEQ * HDIM];
__device__ __half g_Kh[(size_t)BATCH * NHEAD * T_SEQ * HDIM];
__device__ __half g_Vh[(size_t)BATCH * NHEAD * T_SEQ * HDIM];
__device__ __half g_Yh[(size_t)BATCH * T_SEQ * CDIM];   // [b][c][t]

// ===========================================================================
// helpers
// ===========================================================================
__device__ __forceinline__ uint32_t smem_to_u32(const void* p) {
    uint32_t a;
    asm("{ .reg .u64 t; cvta.to.shared.u64 t, %1; cvt.u32.u64 %0, t; }"
        : "=r"(a) : "l"(p));
    return a;
}

__device__ __forceinline__ uint32_t hfp(float a, float b) {
    __half2 t = __floats2half2_rn(a, b);
    return *reinterpret_cast<uint32_t*>(&t);
}
__device__ __forceinline__ float hres(float a) {
    return a - __half2float(__float2half_rn(a));
}

#define LDMX4(r0, r1, r2, r3, addr) \
    asm volatile("ldmatrix.sync.aligned.m8n8.x4.shared.b16 {%0,%1,%2,%3}, [%4];" \
                 : "=r"(r0), "=r"(r1), "=r"(r2), "=r"(r3) : "r"(addr))

#define LDMX4T(r0, r1, r2, r3, addr) \
    asm volatile("ldmatrix.sync.aligned.m8n8.x4.trans.shared.b16 {%0,%1,%2,%3}, [%4];" \
                 : "=r"(r0), "=r"(r1), "=r"(r2), "=r"(r3) : "r"(addr))

#define MMA16816(c, a, b0, b1) \
    asm volatile("mma.sync.aligned.m16n8k16.row.col.f32.f16.f16.f32 " \
                 "{%0,%1,%2,%3}, {%4,%5,%6,%7}, {%8,%9}, {%0,%1,%2,%3};" \
                 : "+f"((c)[0]), "+f"((c)[1]), "+f"((c)[2]), "+f"((c)[3]) \
                 : "r"((a)[0]), "r"((a)[1]), "r"((a)[2]), "r"((a)[3]), \
                   "r"(b0), "r"(b1))

#define STSV4(addr, a, b, cc, d) \
    asm volatile("st.shared.v4.b32 [%0], {%1,%2,%3,%4};" \
                 :: "r"(addr), "r"(a), "r"(b), "r"(cc), "r"(d) : "memory")

#define CPASYNC16(saddr, gptr) \
    asm volatile("cp.async.cg.shared.global [%0], [%1], 16;" \
                 :: "r"(saddr), "l"(gptr) : "memory")
#define CPCOMMIT() asm volatile("cp.async.commit_group;" ::: "memory")
#define CPWAIT1()  asm volatile("cp.async.wait_group 1;" ::: "memory")
#define CPWAIT0()  asm volatile("cp.async.wait_group 0;" ::: "memory")

// ===========================================================================
// fused fp32 -> fp16 conversion: x + 4 weights, all hi-only, ONE launch
// ===========================================================================
#define N4X (MROWS * CDIM / 4)
#define N4W (CDIM * CDIM / 4)

__global__ void cvt_all(const float* __restrict__ x, __half* __restrict__ xh,
                        const float* __restrict__ Wq, const float* __restrict__ Wk,
                        const float* __restrict__ Wv, const float* __restrict__ Wp,
                        __half* __restrict__ Wh)
{
    const int i = blockIdx.x * blockDim.x + threadIdx.x;
    if (i < N4X) {
        const float4 v = ((const float4*)x)[i];
        uint2 h;
        h.x = hfp(v.x, v.y); h.y = hfp(v.z, v.w);
        ((uint2*)xh)[i] = h;
    } else {
        const int j = i - N4X;
        const int mat = j >> 20;            // j / N4W (N4W = 2^20)
        const int k   = j & (N4W - 1);
        if (mat < 4) {
            const float* W = (mat == 0) ? Wq : (mat == 1) ? Wk
                                             : (mat == 2) ? Wv : Wp;
            const float4 v = ((const float4*)W)[k];
            uint2 h;
            h.x = hfp(v.x, v.y); h.y = hfp(v.z, v.w);
            ((uint2*)(Wh + (size_t)mat * CDIM * CDIM))[k] = h;
        }
    }
}

// ===========================================================================
// Tensor-core GEMM, fp16 1-pass: C(M,N) = A(M,K) @ W(N,K)^T + bias(N).
// CTA tile 128x128, warp tile 32x64 (8 warps = 4m x 2n), K-chunk 64,
// 3-stage cp.async pipeline (96KB) -> 2 CTAs/SM, 1 sync/chunk.
// MODE 0: fp32 C out (grid 16 x 32).  MODE 1: fused QKV (grid.x=48, mat=bx>>4)
// Per-stage (32KB): Ah 0 (16K), Bh 16K (16K).
// ===========================================================================
#define GEMM_SMEM_BYTES 98304

template <int MODE>
__global__ void __launch_bounds__(256, 2)
gemm_h(const __half* __restrict__ Ah, const __half* __restrict__ Wh,
       const float* __restrict__ b0, const float* __restrict__ b1,
       const float* __restrict__ b2,
       float* __restrict__ C,
       __half* __restrict__ Qo, __half* __restrict__ Ko, __half* __restrict__ Vo)
{
    extern __shared__ __align__(1024) char sm[];
    const uint32_t sbase = smem_to_u32(sm);

    const int tid  = threadIdx.x;
    const int wid  = tid >> 5;
    const int lane = tid & 31;
    const int wm   = wid >> 1;        // 0..3 -> rows wm*32
    const int wn   = wid & 1;         // 0..1 -> cols wn*64
    const int quad = lane >> 3;
    const int rr   = lane & 7;
    const int mat  = (MODE == 1) ? ((int)blockIdx.x >> 4) : 0;
    const int nbx  = (MODE == 1) ? ((int)blockIdx.x & 15) : (int)blockIdx.x;
    const int mBase = blockIdx.y * 128;
    const int nBase = nbx * 128;

    const __half* Agh = Ah + (size_t)mBase * CDIM;
    const __half* Bgh = Wh + (size_t)mat * CDIM * CDIM + (size_t)nBase * CDIM;
    const float* bias = (MODE == 0) ? b0 : (mat == 0 ? b0 : (mat == 1 ? b1 : b2));

    float c[2][8][4];
#pragma unroll
    for (int mi = 0; mi < 2; mi++)
#pragma unroll
        for (int ni = 0; ni < 8; ni++)
#pragma unroll
            for (int k = 0; k < 4; k++) c[mi][ni][k] = 0.f;

    const int arow0 = wm * 32 + (quad & 1) * 8 + rr;
    const int acolq = (quad >> 1) * 8;
    const int brow0 = wn * 64 + (quad >> 1) * 8 + rr;
    const int bcolq = (quad & 1) * 8;

    auto stage_load = [&](int kt, int stg) {
        const uint32_t base = sbase + (uint32_t)stg * 32768u;
#pragma unroll
        for (int i = 0; i < 4; i++) {
            const int idx = tid + 256 * i;
            const int r = idx >> 3, g = idx & 7;
            const uint32_t off = (uint32_t)(r * 128 + g * 16);
            const uint32_t sw  = off ^ ((off >> 3) & 0x70);
            const size_t e = (size_t)r * CDIM + kt * 64 + g * 8;
            CPASYNC16(base + sw,          (const char*)(Agh + e));
            CPASYNC16(base + 16384u + sw, (const char*)(Bgh + e));
        }
    };

    auto compute = [&](int stg) {
        const uint32_t base = sbase + (uint32_t)stg * 32768u;
        const uint32_t AhS = base, BhS = base + 16384u;
#pragma unroll
        for (int sub = 0; sub < 4; sub++) {
            const int kb = sub * 16;
            uint32_t bh[16];
#pragma unroll
            for (int p = 0; p < 4; p++) {
                const uint32_t off = (uint32_t)((brow0 + p * 16) * 128 + (kb + bcolq) * 2);
                const uint32_t sw  = off ^ ((off >> 3) & 0x70);
                LDMX4(bh[4 * p], bh[4 * p + 1], bh[4 * p + 2], bh[4 * p + 3], BhS + sw);
            }
#pragma unroll
            for (int mi = 0; mi < 2; mi++) {
                uint32_t ah[4];
                const uint32_t off = (uint32_t)((arow0 + mi * 16) * 128 + (kb + acolq) * 2);
                const uint32_t sw  = off ^ ((off >> 3) & 0x70);
                LDMX4(ah[0], ah[1], ah[2], ah[3], AhS + sw);
#pragma unroll
                for (int ni = 0; ni < 8; ni++)
                    MMA16816(c[mi][ni], ah, bh[2 * ni], bh[2 * ni + 1]);
            }
        }
    };

    stage_load(0, 0); CPCOMMIT();
    stage_load(1, 1); CPCOMMIT();

    int stg = 0;
    for (int kt = 0; kt < 32; kt++) {
        if (kt + 1 < 32) { CPWAIT1(); } else { CPWAIT0(); }
        __syncthreads();
        if (kt + 2 < 32) {
            int ns = stg + 2; if (ns >= 3) ns -= 3;
            stage_load(kt + 2, ns);
            CPCOMMIT();
        }
        compute(stg);
        if (++stg == 3) stg = 0;
    }

    // epilogue: fragments -> smem Ct[128][132] fp32 -> gmem
    __syncthreads();
    float* Ct = (float*)sm;
    const int g2 = lane >> 2, t2 = (lane & 3) * 2;
#pragma unroll
    for (int mi = 0; mi < 2; mi++) {
        const int row = wm * 32 + mi * 16 + g2;
#pragma unroll
        for (int ni = 0; ni < 8; ni++) {
            const int col = wn * 64 + ni * 8 + t2;
            Ct[row * 132 + col]           = c[mi][ni][0];
            Ct[row * 132 + col + 1]       = c[mi][ni][1];
            Ct[(row + 8) * 132 + col]     = c[mi][ni][2];
            Ct[(row + 8) * 132 + col + 1] = c[mi][ni][3];
        }
    }
    __syncthreads();

    for (int idx = tid; idx < 128 * 32; idx += 256) {
        const int row = idx >> 5, c4 = (idx & 31) * 4;
        const int n = nBase + c4;
        const float4 bv = *(const float4*)&bias[n];
        float4 v;
        v.x = Ct[row * 132 + c4]     + bv.x;
        v.y = Ct[row * 132 + c4 + 1] + bv.y;
        v.z = Ct[row * 132 + c4 + 2] + bv.z;
        v.w = Ct[row * 132 + c4 + 3] + bv.w;
        const int m = mBase + row;
        if (MODE == 0) {
            *(float4*)&C[(size_t)m * CDIM + n] = v;
        } else {
            const int b = m >> 11, t = m & (T_SEQ - 1);
            const int h = n >> 7, d = n & (HDIM - 1);
            const size_t e = (((size_t)(b * NHEAD + h)) * T_SEQ + t) * HDIM + d;
            uint2 hh;
            hh.x = hfp(v.x, v.y); hh.y = hfp(v.z, v.w);
            __half* dst = (mat == 0) ? Qo : (mat == 1) ? Ko : Vo;
            *(uint2*)(dst + e) = hh;
        }
    }
}

// ===========================================================================
// FA2-style tensor-core flash attention, causal, fp16.
// BQ=128, 256 threads (8 warps), Q fp16 1-pass (32KB smem), K/V cp.async
// double-buffered (2x32KB), P hi/lo in regs. 96KB smem, 1 CTA/SM.
// launch_bounds(256,1): NO register cap -> no spills (fix for R14).
// ===========================================================================
#define ATTN_SMEM_BYTES 98304

__global__ void __launch_bounds__(256, 1)
attn_mma(const __half* __restrict__ Qh,
         const __half* __restrict__ Kh, const __half* __restrict__ Vh,
         __half* __restrict__ Yh)
{
    extern __shared__ __align__(1024) char sm[];
    const uint32_t sb = smem_to_u32(sm);
    const uint32_t QHs = sb;                 // 32KB

    const int tid  = threadIdx.x;
    const int lane = tid & 31;
    const int w    = tid >> 5;
    const int quad = lane >> 3;
    const int rr   = lane & 7;
    const int g    = lane >> 2;
    const int tq   = lane & 3;
    const int qb   = (int)gridDim.x - 1 - (int)blockIdx.x;  // heavy first
    const int bh   = blockIdx.y;

    const size_t headbase = (size_t)bh * T_SEQ * HDIM;
    const int jend = 2 * qb + 1;

    auto stage_kv = [&](int jb, int b) {
        const size_t base = headbase + (size_t)jb * 64 * HDIM;
        const char* kh = (const char*)(Kh + base);
        const char* vh = (const char*)(Vh + base);
        const uint32_t bufb = sb + 32768u + (uint32_t)b * 32768u;
#pragma unroll
        for (int i = 0; i < 4; i++) {
            const int c = tid + 256 * i;
            const int row = c >> 4, gg = c & 15;
            const uint32_t off = (uint32_t)row * 256u +
                                 ((uint32_t)(gg * 16) ^ ((uint32_t)(row & 7) << 4));
            const size_t gb = (size_t)c * 16;
            CPASYNC16(bufb + off,          kh + gb);
            CPASYNC16(bufb + 16384u + off, vh + gb);
        }
    };

    stage_kv(0, 0);
    CPCOMMIT();
    {
        const size_t base = headbase + (size_t)qb * 128 * HDIM;
        const uint4* qh4 = (const uint4*)(Qh + base);
#pragma unroll
        for (int i = 0; i < 8; i++) {
            const int c = tid + 256 * i;
            const int row = c >> 4, gg = c & 15;
            const uint32_t off = (uint32_t)row * 256u +
                                 ((uint32_t)(gg * 16) ^ ((uint32_t)(row & 7) << 4));
            const uint4 vh = qh4[c];
            STSV4(QHs + off, vh.x, vh.y, vh.z, vh.w);
        }
    }

    float o[16][4];
#pragma unroll
    for (int nd = 0; nd < 16; nd++)
#pragma unroll
        for (int k = 0; k < 4; k++) o[nd][k] = 0.f;
    float m_i[2] = {-1e30f, -1e30f}, l_i[2] = {0.f, 0.f};

    const float scale = 0.08838834764831845f;   // 1/sqrt(128)
    const int R0 = qb * 128 + w * 16;

    for (int jb = 0; jb <= jend; jb++) {
        const int buf = jb & 1;
        if (jb < jend) { stage_kv(jb + 1, buf ^ 1); CPCOMMIT(); }
        if (jb < jend) { CPWAIT1(); } else { CPWAIT0(); }
        __syncthreads();

        if (jb * 64 <= R0 + 15) {
            const uint32_t KHb = sb + 32768u + (uint32_t)buf * 32768u;
            const uint32_t VHb = KHb + 16384u;

            // ---- S = Q K^T : 16 rows x 64 keys, 1-pass fp16 ----
            float s[8][4];
#pragma unroll
            for (int ni = 0; ni < 8; ni++)
#pragma unroll
                for (int k = 0; k < 4; k++) s[ni][k] = 0.f;

#pragma unroll
            for (int kb = 0; kb < 8; kb++) {
                uint32_t ah[4];
                {
                    const int arow = w * 16 + (quad & 1) * 8 + rr;
                    const uint32_t cb = (uint32_t)(kb * 32 + (quad >> 1) * 16);
                    const uint32_t off = (uint32_t)arow * 256u +
                                         (cb ^ ((uint32_t)(arow & 7) << 4));
                    LDMX4(ah[0], ah[1], ah[2], ah[3], QHs + off);
                }
#pragma unroll
                for (int p = 0; p < 4; p++) {
                    uint32_t bh2[4];
                    const int krow = p * 16 + (quad >> 1) * 8 + rr;
                    const uint32_t cb = (uint32_t)(kb * 32 + (quad & 1) * 16);
                    const uint32_t off = (uint32_t)krow * 256u +
                                         (cb ^ ((uint32_t)(krow & 7) << 4));
                    LDMX4(bh2[0], bh2[1], bh2[2], bh2[3], KHb + off);
                    MMA16816(s[2 * p],     ah, bh2[0], bh2[1]);
                    MMA16816(s[2 * p + 1], ah, bh2[2], bh2[3]);
                }
            }

            // ---- scale + causal mask ----
            const bool needmask = (jb * 64 + 63 > R0);
#pragma unroll
            for (int ni = 0; ni < 8; ni++)
#pragma unroll
                for (int j = 0; j < 4; j++) {
                    float v = s[ni][j] * scale;
                    if (needmask) {
                        const int rglob = R0 + g + ((j >> 1) << 3);
                        const int kglob = jb * 64 + ni * 8 + 2 * tq + (j & 1);
                        if (kglob > rglob) v = -1e30f;
                    }
                    s[ni][j] = v;
                }

            // ---- warp-local online softmax (rows g, g+8) ----
            float alpha[2];
#pragma unroll
            for (int r = 0; r < 2; r++) {
                float mx = -1e30f;
#pragma unroll
                for (int ni = 0; ni < 8; ni++)
                    mx = fmaxf(mx, fmaxf(s[ni][2 * r], s[ni][2 * r + 1]));
                mx = fmaxf(mx, __shfl_xor_sync(0xffffffffu, mx, 1));
                mx = fmaxf(mx, __shfl_xor_sync(0xffffffffu, mx, 2));
                const float mn = fmaxf(m_i[r], mx);
                alpha[r] = __expf(m_i[r] - mn);
                m_i[r] = mn;
                float sum = 0.f;
#pragma unroll
                for (int ni = 0; ni < 8; ni++) {
                    const float p0 = __expf(s[ni][2 * r] - mn);
                    const float p1 = __expf(s[ni][2 * r + 1] - mn);
                    s[ni][2 * r] = p0; s[ni][2 * r + 1] = p1;
                    sum += p0 + p1;
                }
                sum += __shfl_xor_sync(0xffffffffu, sum, 1);
                sum += __shfl_xor_sync(0xffffffffu, sum, 2);
                l_i[r] = l_i[r] * alpha[r] + sum;
#pragma unroll
                for (int nd = 0; nd < 16; nd++) {
                    o[nd][2 * r]     *= alpha[r];
                    o[nd][2 * r + 1] *= alpha[r];
                }
            }

            // ---- O += P V : P hi/lo packed in regs, V fp16 (2-pass) ----
#pragma unroll
            for (int kc = 0; kc < 4; kc++) {
                uint32_t aph[4], apl[4];
                const float* s0 = s[2 * kc];
                const float* s1 = s[2 * kc + 1];
                aph[0] = hfp(s0[0], s0[1]);
                aph[1] = hfp(s0[2], s0[3]);
                aph[2] = hfp(s1[0], s1[1]);
                aph[3] = hfp(s1[2], s1[3]);
                apl[0] = hfp(hres(s0[0]), hres(s0[1]));
                apl[1] = hfp(hres(s0[2]), hres(s0[3]));
                apl[2] = hfp(hres(s1[0]), hres(s1[1]));
                apl[3] = hfp(hres(s1[2]), hres(s1[3]));
#pragma unroll
                for (int nd = 0; nd < 8; nd++) {
                    const int key = kc * 16 + (quad & 1) * 8 + rr;
                    const uint32_t db = (uint32_t)(nd * 32 + (quad >> 1) * 16);
                    const uint32_t off = (uint32_t)key * 256u +
                                         (db ^ ((uint32_t)(key & 7) << 4));
                    uint32_t vh[4];
                    LDMX4T(vh[0], vh[1], vh[2], vh[3], VHb + off);
                    MMA16816(o[2 * nd],     aph, vh[0], vh[1]);
                    MMA16816(o[2 * nd],     apl, vh[0], vh[1]);
                    MMA16816(o[2 * nd + 1], aph, vh[2], vh[3]);
                    MMA16816(o[2 * nd + 1], apl, vh[2], vh[3]);
                }
            }
        }
        __syncthreads();
    }

    // ---- epilogue: normalize, transpose-stage, store Y fp16 [d][t] ----
    const float inv0 = 1.f / l_i[0], inv1 = 1.f / l_i[1];
    float* Od = (float*)sm;   // [128 d][132]
#pragma unroll
    for (int nd = 0; nd < 16; nd++) {
        const int d = nd * 8 + 2 * tq;
        const int t0 = w * 16 + g;
        Od[d * 132 + t0]           = o[nd][0] * inv0;
        Od[(d + 1) * 132 + t0]     = o[nd][1] * inv0;
        Od[d * 132 + t0 + 8]       = o[nd][2] * inv1;
        Od[(d + 1) * 132 + t0 + 8] = o[nd][3] * inv1;
    }
    __syncthreads();

    const int b = bh >> 4, h = bh & 15;
    const size_t ybase = ((size_t)(b * CDIM + h * HDIM)) * T_SEQ + (size_t)qb * 128;
    for (int idx = tid; idx < 128 * 32; idx += 256) {
        const int d = idx >> 5, q4 = (idx & 31) * 4;
        const float4 v = *(const float4*)&Od[d * 132 + q4];
        uint2 hh;
        hh.x = hfp(v.x, v.y); hh.y = hfp(v.z, v.w);
        *(uint2*)(Yh + ybase + (size_t)d * T_SEQ + q4) = hh;
    }
}

// ===========================================================================
extern "C" void kernel_launch(void* const* d_in, const int* in_sizes, int n_in,
                              void* d_out, int out_size)
{
    (void)in_sizes; (void)n_in; (void)out_size;
    const float* x  = (const float*)d_in[0];
    const float* Wq = (const float*)d_in[1];
    const float* bq = (const float*)d_in[2];
    const float* Wk = (const float*)d_in[3];
    const float* bk = (const float*)d_in[4];
    const float* Wv = (const float*)d_in[5];
    const float* bv = (const float*)d_in[6];
    const float* Wp = (const float*)d_in[7];
    const float* bp = (const float*)d_in[8];
    float* out = (float*)d_out;

    __half *xh, *Wh, *Qh, *Kh, *Vh, *Yh;
    cudaGetSymbolAddress((void**)&xh, g_xh);
    cudaGetSymbolAddress((void**)&Wh, g_Wh);
    cudaGetSymbolAddress((void**)&Qh, g_Qh);
    cudaGetSymbolAddress((void**)&Kh, g_Kh);
    cudaGetSymbolAddress((void**)&Vh, g_Vh);
    cudaGetSymbolAddress((void**)&Yh, g_Yh);

    cudaFuncSetAttribute(gemm_h<0>, cudaFuncAttributeMaxDynamicSharedMemorySize,
                         GEMM_SMEM_BYTES);
    cudaFuncSetAttribute(gemm_h<1>, cudaFuncAttributeMaxDynamicSharedMemorySize,
                         GEMM_SMEM_BYTES);
    cudaFuncSetAttribute(attn_mma, cudaFuncAttributeMaxDynamicSharedMemorySize,
                         ATTN_SMEM_BYTES);

    const size_t WSZ = (size_t)CDIM * CDIM;

    // fused conversion pass (x + all 4 weights, fp16)
    {
        const int total = N4X + 4 * N4W;
        cvt_all<<<(total + 255) / 256, 256>>>(x, xh, Wq, Wk, Wv, Wp, Wh);
    }

    // fused QKV GEMM: grid.x = 3 mats x 16 n-tiles, grid.y = 32 m-tiles
    gemm_h<1><<<dim3(48, MROWS / 128), 256, GEMM_SMEM_BYTES>>>(
        xh, Wh, bq, bk, bv, nullptr, Qh, Kh, Vh);

    attn_mma<<<dim3(T_SEQ / 128, BATCH * NHEAD), 256, ATTN_SMEM_BYTES>>>(
        Qh, Kh, Vh, Yh);

    gemm_h<0><<<dim3(16, MROWS / 128), 256, GEMM_SMEM_BYTES>>>(
        Yh, Wh + 3 * WSZ, bp, nullptr, nullptr, out,
        nullptr, nullptr, nullptr);
}